// round 2
// baseline (speedup 1.0000x reference)
#include <cuda_runtime.h>
#include <math.h>

// out[b][i] = cos(theta_i) * (2*P_i/T - 1)
//   T   = sum_k x_k^2 (NaN-scrubbed)
//   P_i = sum of x_k^2 over k with bit (3-i) of k == 0   (wire 0 = MSB)
// Derivation: RX on each wire commutes past the other wires; for a REAL
// state <Y> = 0, so <Z_i> after RX(t_i) is cos(t_i) * <Z_i>_before.
//
// Single fused kernel: per-block cosf into smem (4 MUFU ops per block),
// 2 samples per thread (8 front-batched LDG.128), streaming cache hints.
__global__ void __launch_bounds__(256) quantum_z_kernel(
    const float4* __restrict__ x, float4* __restrict__ out,
    const float* __restrict__ qw, int B)
{
    __shared__ float sc[4];
    if (threadIdx.x < 4) sc[threadIdx.x] = cosf(qw[threadIdx.x]);
    __syncthreads();

    int b0 = (blockIdx.x * blockDim.x + threadIdx.x) * 2;
    if (b0 >= B) return;

    const float4* p = x + (size_t)b0 * 4;

    // Front-batch all 8 loads (2 samples x 64B) for max MLP.
    float4 v[8];
    #pragma unroll
    for (int i = 0; i < 8; ++i) v[i] = __ldcs(&p[i]);

    float c0 = sc[0], c1 = sc[1], c2 = sc[2], c3 = sc[3];

    #pragma unroll
    for (int s = 0; s < 2; ++s) {
        float e[16];
        #pragma unroll
        for (int q = 0; q < 4; ++q) {
            float4 vv = v[s * 4 + q];
            e[q*4+0] = vv.x; e[q*4+1] = vv.y; e[q*4+2] = vv.z; e[q*4+3] = vv.w;
        }

        float sq[16];
        #pragma unroll
        for (int k = 0; k < 16; ++k) {
            float xv = e[k];
            xv = (xv != xv) ? 0.0f : xv;   // NaN scrub (matches reference)
            sq[k] = xv * xv;
        }

        float T = 0.0f;
        #pragma unroll
        for (int k = 0; k < 16; ++k) T += sq[k];

        // P_i = sum of sq[k] where bit (3-i) of k is zero
        float P0 = sq[0]+sq[1]+sq[2]+sq[3]+sq[4]+sq[5]+sq[6]+sq[7];
        float P1 = sq[0]+sq[1]+sq[2]+sq[3]+sq[8]+sq[9]+sq[10]+sq[11];
        float P2 = sq[0]+sq[1]+sq[4]+sq[5]+sq[8]+sq[9]+sq[12]+sq[13];
        float P3 = sq[0]+sq[2]+sq[4]+sq[6]+sq[8]+sq[10]+sq[12]+sq[14];

        float invT = 1.0f / T;

        float4 r;
        r.x = c0 * fmaf(2.0f * P0, invT, -1.0f);
        r.y = c1 * fmaf(2.0f * P1, invT, -1.0f);
        r.z = c2 * fmaf(2.0f * P2, invT, -1.0f);
        r.w = c3 * fmaf(2.0f * P3, invT, -1.0f);

        __stcs(&out[b0 + s], r);
    }
}

extern "C" void kernel_launch(void* const* d_in, const int* in_sizes, int n_in,
                              void* d_out, int out_size) {
    const float* x  = (const float*)d_in[0];
    const float* qw = (const float*)d_in[1];
    float* out = (float*)d_out;

    int B = in_sizes[0] / 16;                 // 2^21 samples
    int threads = 256;
    int samples_per_block = threads * 2;
    int blocks = (B + samples_per_block - 1) / samples_per_block;

    quantum_z_kernel<<<blocks, threads>>>(
        (const float4*)x, (float4*)out, qw, B);
}

// round 3
// speedup vs baseline: 1.2821x; 1.2821x over previous
#include <cuda_runtime.h>
#include <math.h>

// out[b][i] = cos(theta_i) * Z_i / T
//   T   = sum_k x_k^2 (NaN-scrubbed),  Z_i = sum_k sign_i(k) x_k^2,
//   sign_i(k) = +1 if bit (3-i) of k == 0  (wire 0 = MSB).
//
// Quad-cooperative layout: 4 consecutive lanes own one sample (one float4
// each -> element k = (lane&3)*4 + comp, so k bit3 = lane bit1, k bit2 =
// lane bit0, k bits 1:0 = component bits). Signed shfl.xor butterflies
// produce Z0..Z3 and T in every lane; lane j writes output component j.
// Every LDG.128 is warp-contiguous (512B) -> minimal L1 wavefronts.
__global__ void __launch_bounds__(256) quantum_z_kernel(
    const float4* __restrict__ x, float* __restrict__ out,
    const float* __restrict__ qw, int B)
{
    __shared__ float sc[4];
    if (threadIdx.x < 4) sc[threadIdx.x] = cosf(qw[threadIdx.x]);
    __syncthreads();

    int gtid   = blockIdx.x * blockDim.x + threadIdx.x;
    int warpId = gtid >> 5;
    int lane   = threadIdx.x & 31;

    if (warpId * 32 >= B) return;   // warp tile = 32 samples (B % 32 == 0 here)

    const float4* base = x + (size_t)warpId * 128;   // 32 samples * 4 float4
    float* obase = out + (size_t)warpId * 128;       // 32 samples * 4 floats

    // Front-batch 4 fully-coalesced loads (MLP=4).
    float4 v[4];
    #pragma unroll
    for (int g = 0; g < 4; ++g) v[g] = base[g * 32 + lane];

    float c = sc[lane & 3];          // this lane always emits wire (lane&3)
    float neg0 = (lane & 1) ? -1.0f : 1.0f;   // sign for wire-1 butterfly
    float neg1 = (lane & 2) ? -1.0f : 1.0f;   // sign for wire-0 butterfly
    int j = lane & 3;

    #pragma unroll
    for (int g = 0; g < 4; ++g) {
        float a0 = v[g].x, a1 = v[g].y, a2 = v[g].z, a3 = v[g].w;
        a0 = (a0 != a0) ? 0.0f : a0;   // NaN scrub (matches reference)
        a1 = (a1 != a1) ? 0.0f : a1;
        a2 = (a2 != a2) ? 0.0f : a2;
        a3 = (a3 != a3) ? 0.0f : a3;
        float s0 = a0 * a0, s1 = a1 * a1, s2 = a2 * a2, s3 = a3 * a3;

        float t  = (s0 + s1) + (s2 + s3);
        float z2 = (s0 + s1) - (s2 + s3);   // wire 2: k bit1 = component bit1
        float z3 = (s0 - s1) + (s2 - s3);   // wire 3: k bit0 = component bit0

        // Stage 1: combine across lane bit0 (k bit2 -> wire 1)
        float z1 = neg0 * t;
        z1 += __shfl_xor_sync(0xFFFFFFFFu, z1, 1);
        t  += __shfl_xor_sync(0xFFFFFFFFu, t , 1);
        z2 += __shfl_xor_sync(0xFFFFFFFFu, z2, 1);
        z3 += __shfl_xor_sync(0xFFFFFFFFu, z3, 1);

        // Stage 2: combine across lane bit1 (k bit3 -> wire 0)
        float z0 = neg1 * t;
        z0 += __shfl_xor_sync(0xFFFFFFFFu, z0, 2);
        t  += __shfl_xor_sync(0xFFFFFFFFu, t , 2);
        z1 += __shfl_xor_sync(0xFFFFFFFFu, z1, 2);
        z2 += __shfl_xor_sync(0xFFFFFFFFu, z2, 2);
        z3 += __shfl_xor_sync(0xFFFFFFFFu, z3, 2);

        float zj = (j == 0) ? z0 : (j == 1) ? z1 : (j == 2) ? z2 : z3;

        obase[g * 32 + lane] = c * zj / t;   // 128B contiguous per warp-store
    }
}

extern "C" void kernel_launch(void* const* d_in, const int* in_sizes, int n_in,
                              void* d_out, int out_size) {
    const float* x  = (const float*)d_in[0];
    const float* qw = (const float*)d_in[1];
    float* out = (float*)d_out;

    int B = in_sizes[0] / 16;                 // 2^21 samples
    // One warp handles 32 samples; 256-thread blocks -> 256 samples/block.
    int blocks = (B + 255) / 256;

    quantum_z_kernel<<<blocks, 256>>>(
        (const float4*)x, out, qw, B);
}

// round 4
// speedup vs baseline: 1.4898x; 1.1620x over previous
#include <cuda_runtime.h>
#include <math.h>

// out[b][i] = cos(theta_i) * Z_i / T
//   T   = sum_k x_k^2 (NaN-scrubbed),  Z_i = sum_k sign_i(k) x_k^2,
//   sign_i(k) = +1 if bit (3-i) of k == 0  (wire 0 = MSB).
//
// Quad-cooperative: 4 lanes per sample, element k = (lane&3)*4 + comp.
//   k bit3 = lane bit1 (wire 0), k bit2 = lane bit0 (wire 1),
//   k bits 1:0 = component bits (wires 2,3).
// 5 shuffles per group: one xor-1 butterfly on t gives BOTH the pair-sum
// (-> T, Z0) and the signed pair-difference (-> Z1); z2/z3 share one
// payload-swapped butterfly. Lane j writes component j^2 (coalesced 128B).
__global__ void __launch_bounds__(256) quantum_z_kernel(
    const float4* __restrict__ x, float* __restrict__ out,
    const float* __restrict__ qw, int B)
{
    __shared__ float sc[4];
    if (threadIdx.x < 4) sc[threadIdx.x] = cosf(qw[threadIdx.x]);
    __syncthreads();

    int gtid   = blockIdx.x * blockDim.x + threadIdx.x;
    int warpId = gtid >> 5;
    int lane   = threadIdx.x & 31;

    if (warpId * 32 >= B) return;   // warp tile = 32 samples (B % 32 == 0)

    const float4* base = x + (size_t)warpId * 128;   // 32 samples * 4 float4
    float* obase = out + (size_t)warpId * 128;

    float4 v[4];
    #pragma unroll
    for (int g = 0; g < 4; ++g) v[g] = __ldcs(&base[g * 32 + lane]);

    int   j    = lane & 3;
    float c    = sc[j ^ 2];                    // lane j emits wire j^2
    float neg0 = (lane & 1) ? -1.0f : 1.0f;    // sign for k bit2 (wire 1)
    float neg1 = (lane & 2) ? -1.0f : 1.0f;    // sign for k bit3 (wire 0)
    bool  odd  = (lane & 1);

    #pragma unroll
    for (int g = 0; g < 4; ++g) {
        float a0 = v[g].x, a1 = v[g].y, a2 = v[g].z, a3 = v[g].w;
        a0 = (a0 != a0) ? 0.0f : a0;   // NaN scrub (matches reference)
        a1 = (a1 != a1) ? 0.0f : a1;
        a2 = (a2 != a2) ? 0.0f : a2;
        a3 = (a3 != a3) ? 0.0f : a3;
        float s0 = a0 * a0, s1 = a1 * a1, s2 = a2 * a2, s3 = a3 * a3;

        float p01 = s0 + s1, p23 = s2 + s3;
        float t     = p01 + p23;
        float z2loc = p01 - p23;               // wire 2 (comp bit1)
        float z3loc = (s0 - s1) + (s2 - s3);   // wire 3 (comp bit0)

        // Stage 1 over lane bit0: pair-sum AND signed pair-diff from ONE shfl
        float sh1 = __shfl_xor_sync(0xFFFFFFFFu, t, 1);
        float tp  = t + sh1;                   // pair sum
        float z1p = neg0 * (t - sh1);          // wire-1 partial (pair-const)

        // z2/z3 shared butterfly: send what the partner needs
        float w   = odd ? z2loc : z3loc;
        float sh4 = __shfl_xor_sync(0xFFFFFFFFu, w, 1);
        float m   = (odd ? z3loc : z2loc) + sh4;   // even: z2 pair, odd: z3 pair

        // Stage 2 over lane bit1
        float sh2 = __shfl_xor_sync(0xFFFFFFFFu, tp, 2);
        float T   = tp + sh2;
        float Z0  = neg1 * (tp - sh2);
        float sh3 = __shfl_xor_sync(0xFFFFFFFFu, z1p, 2);
        float Z1  = z1p + sh3;
        float sh5 = __shfl_xor_sync(0xFFFFFFFFu, m, 2);
        float Zm  = m + sh5;                   // even lanes: Z2, odd: Z3

        // lane j -> component j^2:  j=0:Z2, j=1:Z3, j=2:Z0, j=3:Z1
        float Z = (j < 2) ? Zm : ((j == 2) ? Z0 : Z1);

        obase[g * 32 + (lane ^ 2)] = c * __fdividef(Z, T);
    }
}

extern "C" void kernel_launch(void* const* d_in, const int* in_sizes, int n_in,
                              void* d_out, int out_size) {
    const float* x  = (const float*)d_in[0];
    const float* qw = (const float*)d_in[1];
    float* out = (float*)d_out;

    int B = in_sizes[0] / 16;                 // 2^21 samples
    int blocks = (B + 255) / 256;             // 256 samples per block

    quantum_z_kernel<<<blocks, 256>>>(
        (const float4*)x, out, qw, B);
}